// round 9
// baseline (speedup 1.0000x reference)
#include <cuda_runtime.h>
#include <math.h>

#define LSEQ 512
#define HDIM 512
#define NSEQ 64
#define NSTREAM 128
#define GRU_BLOCKS 768

__device__ float g_E[(size_t)NSEQ * LSEQ * 512];
__device__ float g_P[(size_t)5 * LSEQ * 3072];
__device__ float g_GI[(size_t)NSEQ * LSEQ * 3072];
__device__ float g_GHp[(size_t)4 * NSTREAM * 1536];
__device__ float g_H[2][NSTREAM * HDIM];
__device__ float g_ENC[(size_t)NSEQ * LSEQ * 1024];
__device__ float g_N[NSEQ * LSEQ];
__device__ float g_SIM[(size_t)32 * LSEQ * LSEQ];
__device__ float g_MS1[32 * LSEQ], g_RL1[32 * LSEQ];
__device__ float g_MS2[32 * LSEQ], g_RL2[32 * LSEQ];
__device__ float g_FEAT[32 * 768];
__device__ unsigned g_bar_cnt;
__device__ unsigned g_bar_gen;

// ---- K0: P[s][idx][n] = sum_k pe[idx,k] * Wih[n, 512+64s+k] ----
__global__ __launch_bounds__(256) void pe_tables(const float* __restrict__ pe,
                                                 const float* __restrict__ W) {
    int n0 = blockIdx.x * 128, l0 = blockIdx.y * 16, s = blockIdx.z;
    __shared__ float Ws[64][129];
    __shared__ float Pes[16][64];
    int tid = threadIdx.x;
    for (int i = tid; i < 64 * 128; i += 256) {
        int n = i >> 6, k = i & 63;
        Ws[k][n] = W[(size_t)(n0 + n) * 832 + 512 + s * 64 + k];
    }
    for (int i = tid; i < 16 * 64; i += 256)
        Pes[i >> 6][i & 63] = pe[(size_t)(l0 + (i >> 6)) * 64 + (i & 63)];
    __syncthreads();
#pragma unroll
    for (int o = 0; o < 8; o++) {
        int idx = tid + o * 256;
        int r = idx >> 7, n = idx & 127;
        float acc = 0.f;
#pragma unroll
        for (int k = 0; k < 64; k++) acc += Pes[r][k] * Ws[k][n];
        g_P[((size_t)s * 512 + l0 + r) * 3072 + n0 + n] = acc;
    }
}

// ---- K1: pack word+pinyin embeddings ----
__global__ void embed_pack(const int* __restrict__ w0, const int* __restrict__ w1,
                           const int* __restrict__ py0, const int* __restrict__ py1,
                           const float* __restrict__ ew, const float* __restrict__ ep) {
    int seq = blockIdx.x, l = blockIdx.y;
    int side = seq >> 5, b = seq & 31;
    const int* wi = side ? w1 : w0;
    const int* pi = side ? py1 : py0;
    int wid = wi[b * 512 + l], pid = pi[b * 512 + l];
    int tid = threadIdx.x;  // 128
    float4 v;
    if (tid < 64) v = *(const float4*)(ew + (size_t)wid * 256 + tid * 4);
    else          v = *(const float4*)(ep + (size_t)pid * 256 + (tid - 64) * 4);
    *(float4*)(g_E + ((size_t)seq * 512 + l) * 512 + tid * 4) = v;
}

// ---- K2: GI = E @ Wih[:, :512]^T + bih + pe-tables.  M=32768 N=3072 K=512 ----
__global__ __launch_bounds__(256) void gemm_gi(
    const float* __restrict__ W, const float* __restrict__ bih,
    const int* __restrict__ tb0, const int* __restrict__ te0,
    const int* __restrict__ tb1, const int* __restrict__ te1) {
    __shared__ float As[16][132];
    __shared__ float Bs[16][132];
    int tid = threadIdx.x;
    int n0 = blockIdx.x * 128, m0 = blockIdx.y * 128;
    int tx = tid % 16, ty = tid / 16;
    const float* A = g_E + (size_t)m0 * 512;
    const float* B = W + (size_t)n0 * 832;
    int lr = tid >> 2, lc = (tid & 3) << 2;
    float acc[8][8];
#pragma unroll
    for (int i = 0; i < 8; i++)
#pragma unroll
        for (int j = 0; j < 8; j++) acc[i][j] = 0.f;

    for (int kc = 0; kc < 32; kc++) {
        int K0 = kc * 16;
        float4 ra0 = *(const float4*)(A + (size_t)lr * 512 + K0 + lc);
        float4 ra1 = *(const float4*)(A + (size_t)(lr + 64) * 512 + K0 + lc);
        float4 rb0 = *(const float4*)(B + (size_t)lr * 832 + K0 + lc);
        float4 rb1 = *(const float4*)(B + (size_t)(lr + 64) * 832 + K0 + lc);
        __syncthreads();
        As[lc+0][lr]=ra0.x; As[lc+1][lr]=ra0.y; As[lc+2][lr]=ra0.z; As[lc+3][lr]=ra0.w;
        As[lc+0][lr+64]=ra1.x; As[lc+1][lr+64]=ra1.y; As[lc+2][lr+64]=ra1.z; As[lc+3][lr+64]=ra1.w;
        Bs[lc+0][lr]=rb0.x; Bs[lc+1][lr]=rb0.y; Bs[lc+2][lr]=rb0.z; Bs[lc+3][lr]=rb0.w;
        Bs[lc+0][lr+64]=rb1.x; Bs[lc+1][lr+64]=rb1.y; Bs[lc+2][lr+64]=rb1.z; Bs[lc+3][lr+64]=rb1.w;
        __syncthreads();
#pragma unroll
        for (int kk = 0; kk < 16; kk++) {
            float4 a0 = *(const float4*)&As[kk][ty * 8];
            float4 a1 = *(const float4*)&As[kk][ty * 8 + 4];
            float4 b0 = *(const float4*)&Bs[kk][tx * 8];
            float4 b1 = *(const float4*)&Bs[kk][tx * 8 + 4];
            float av[8] = {a0.x,a0.y,a0.z,a0.w,a1.x,a1.y,a1.z,a1.w};
            float bv[8] = {b0.x,b0.y,b0.z,b0.w,b1.x,b1.y,b1.z,b1.w};
#pragma unroll
            for (int i = 0; i < 8; i++)
#pragma unroll
                for (int j = 0; j < 8; j++) acc[i][j] += av[i] * bv[j];
        }
    }
    int colb = n0 + tx * 8;
    float bv[8];
#pragma unroll
    for (int j = 0; j < 8; j++) bv[j] = bih[colb + j];
#pragma unroll
    for (int i = 0; i < 8; i++) {
        int row = m0 + ty * 8 + i;
        int seq = row >> 9, l = row & 511;
        int side = seq >> 5, b = seq & 31;
        const int* TB = side ? tb1 : tb0;
        const int* TE = side ? te1 : te0;
        int tb = TB[b * 512 + l], te = TE[b * 512 + l];
        const float* p0 = g_P + ((size_t)0 * 512 + l)        * 3072 + colb;
        const float* p1 = g_P + ((size_t)1 * 512 + tb)       * 3072 + colb;
        const float* p2 = g_P + ((size_t)2 * 512 + te)       * 3072 + colb;
        const float* p3 = g_P + ((size_t)3 * 512 + (te - l)) * 3072 + colb;
        const float* p4 = g_P + ((size_t)4 * 512 + (l - tb)) * 3072 + colb;
        float out[8];
#pragma unroll
        for (int j = 0; j < 8; j++)
            out[j] = acc[i][j] + bv[j] + p0[j] + p1[j] + p2[j] + p3[j] + p4[j];
        float* dst = g_GI + (size_t)row * 3072 + colb;
        *(float4*)dst       = make_float4(out[0], out[1], out[2], out[3]);
        *(float4*)(dst + 4) = make_float4(out[4], out[5], out[6], out[7]);
    }
}

// ---- software grid barrier (all GRU_BLOCKS provably co-resident) ----
__device__ __forceinline__ void grid_bar() {
    __syncthreads();
    if (threadIdx.x == 0) {
        __threadfence();
        unsigned gen = *(volatile unsigned*)&g_bar_gen;
        if (atomicAdd(&g_bar_cnt, 1u) == GRU_BLOCKS - 1u) {
            atomicExch(&g_bar_cnt, 0u);
            __threadfence();
            atomicExch(&g_bar_gen, gen + 1u);
        } else {
            while (*(volatile unsigned*)&g_bar_gen == gen) __nanosleep(32);
        }
        __threadfence();
    }
    __syncthreads();
}

// ---- K3: persistent bidirectional GRU over all 512 steps ----
// Grid: 768 blocks x 64 threads. Block = (gate-tile 32, splitK 4, dir 2, stream-tile 2).
// Whh tile (32 gates x 128 K) is loaded into smem ONCE; per step only h streams load.
__global__ __launch_bounds__(64) void gru_persist(
    const float* __restrict__ Whh, const float* __restrict__ bhh,
    const int* __restrict__ len1, const int* __restrict__ len2) {
    __shared__ float Wpre[128][36];
    __shared__ float Hs[32][36];
    int bx = blockIdx.x, tid = threadIdx.x;
    int nt = bx % 48;
    int kh = (bx / 48) % 4;
    int z  = bx / 192;
    int d = z >> 1, mt = z & 1;
    int g0 = nt * 32;
    int s0 = d * 64 + mt * 32;
    int k0 = kh * 128;
    int tx = tid & 7, ty = tid >> 3;
    const float* Wd = Whh + (size_t)d * 1536 * 512;

    // one-time weight tile preload (coalesced)
    for (int i = tid; i < 4096; i += 64) {
        int m = i >> 7, k = i & 127;
        Wpre[k][m] = Wd[(size_t)(g0 + m) * 512 + k0 + k];
    }
    // zero H[0]
    for (int i = bx * 64 + tid; i < NSTREAM * HDIM; i += GRU_BLOCKS * 64)
        g_H[0][i] = 0.f;
    grid_bar();

    for (int t = 0; t < LSEQ; t++) {
        // ---- phase A: partial gh = Whh_tile @ h ----
        const float* Hc = g_H[t & 1];
        float acc[4][4];
#pragma unroll
        for (int i = 0; i < 4; i++)
#pragma unroll
            for (int j = 0; j < 4; j++) acc[i][j] = 0.f;
        for (int c = 0; c < 128; c += 32) {
#pragma unroll
            for (int i = 0; i < 16; i++) {
                int idx = tid + i * 64;
                int m = idx >> 5, k = idx & 31;
                Hs[k][m] = Hc[(s0 + m) * 512 + k0 + c + k];
            }
            __syncthreads();
#pragma unroll
            for (int k = 0; k < 32; k++) {
                float4 a = *(const float4*)&Hs[k][ty * 4];
                float4 b = *(const float4*)&Wpre[c + k][tx * 4];
                float av[4] = {a.x, a.y, a.z, a.w};
                float bb[4] = {b.x, b.y, b.z, b.w};
#pragma unroll
                for (int i = 0; i < 4; i++)
#pragma unroll
                    for (int j = 0; j < 4; j++) acc[i][j] += av[i] * bb[j];
            }
            __syncthreads();
        }
#pragma unroll
        for (int i = 0; i < 4; i++) {
            int s = s0 + ty * 4 + i;
            float* o = g_GHp + ((size_t)(kh * NSTREAM + s)) * 1536 + g0 + tx * 4;
            *(float4*)o = make_float4(acc[i][0], acc[i][1], acc[i][2], acc[i][3]);
        }
        grid_bar();

        // ---- phase B: gates + state update + output ----
        for (int idx = bx * 64 + tid; idx < NSTREAM * 512; idx += GRU_BLOCKS * 64) {
            int s = idx >> 9, j = idx & 511;
            int dd = s >> 6, seq = s & 63, side = seq >> 5, b = seq & 31;
            int len = side ? len2[b] : len1[b];
            bool valid = (t < len);
            int lp = (dd == 1 && valid) ? (len - 1 - t) : t;
            const float* gi = g_GI + ((size_t)(seq * 512 + lp)) * 3072 + dd * 1536;
            float ghr = 0.f, ghz = 0.f, ghn = 0.f;
#pragma unroll
            for (int p = 0; p < 4; p++) {
                const float* gh = g_GHp + ((size_t)(p * NSTREAM + s)) * 1536;
                ghr += gh[j];
                ghz += gh[512 + j];
                ghn += gh[1024 + j];
            }
            const float* bh = bhh + dd * 1536;
            float h = g_H[t & 1][s * 512 + j];
            float r = 1.f / (1.f + expf(-(gi[j] + ghr + bh[j])));
            float zz = 1.f / (1.f + expf(-(gi[512 + j] + ghz + bh[512 + j])));
            float n = tanhf(gi[1024 + j] + r * (ghn + bh[1024 + j]));
            float hnew = (1.f - zz) * n + zz * h;
            g_H[(t + 1) & 1][s * 512 + j] = valid ? hnew : h;
            g_ENC[((size_t)(seq * 512 + lp)) * 1024 + dd * 512 + j] = valid ? hnew : 0.f;
        }
        grid_bar();
    }
}

// ---- K4: row norms ----
__global__ void norms_kernel() {
    int seq = blockIdx.x;
    int w = threadIdx.x >> 5, lane = threadIdx.x & 31;
    int i = blockIdx.y * 8 + w;
    const float* row = g_ENC + ((size_t)seq * 512 + i) * 1024;
    float sacc = 0.f;
    for (int k = lane; k < 1024; k += 32) { float v = row[k]; sacc += v * v; }
#pragma unroll
    for (int off = 16; off; off >>= 1) sacc += __shfl_down_sync(0xffffffffu, sacc, off);
    if (lane == 0) g_N[seq * 512 + i] = sqrtf(sacc);
}

// ---- K5: SIM[b] = enc1[b] @ enc2[b]^T / max(n1*n2, eps) ----
__global__ __launch_bounds__(256) void sim_gemm() {
    int b = blockIdx.z;
    int n0 = blockIdx.x * 128, m0 = blockIdx.y * 128;
    __shared__ float As[16][132];
    __shared__ float Bs[16][132];
    const float* A  = g_ENC + ((size_t)b * 512 + m0) * 1024;
    const float* Bp = g_ENC + ((size_t)(32 + b) * 512 + n0) * 1024;
    int tid = threadIdx.x;
    int tx = tid % 16, ty = tid / 16;
    int lr = tid >> 2, lc = (tid & 3) << 2;
    float acc[8][8];
#pragma unroll
    for (int i = 0; i < 8; i++)
#pragma unroll
        for (int j = 0; j < 8; j++) acc[i][j] = 0.f;
    for (int kc = 0; kc < 64; kc++) {
        int K0 = kc * 16;
        float4 ra0 = *(const float4*)(A  + (size_t)lr * 1024 + K0 + lc);
        float4 ra1 = *(const float4*)(A  + (size_t)(lr + 64) * 1024 + K0 + lc);
        float4 rb0 = *(const float4*)(Bp + (size_t)lr * 1024 + K0 + lc);
        float4 rb1 = *(const float4*)(Bp + (size_t)(lr + 64) * 1024 + K0 + lc);
        __syncthreads();
        As[lc+0][lr]=ra0.x; As[lc+1][lr]=ra0.y; As[lc+2][lr]=ra0.z; As[lc+3][lr]=ra0.w;
        As[lc+0][lr+64]=ra1.x; As[lc+1][lr+64]=ra1.y; As[lc+2][lr+64]=ra1.z; As[lc+3][lr+64]=ra1.w;
        Bs[lc+0][lr]=rb0.x; Bs[lc+1][lr]=rb0.y; Bs[lc+2][lr]=rb0.z; Bs[lc+3][lr]=rb0.w;
        Bs[lc+0][lr+64]=rb1.x; Bs[lc+1][lr+64]=rb1.y; Bs[lc+2][lr+64]=rb1.z; Bs[lc+3][lr+64]=rb1.w;
        __syncthreads();
#pragma unroll
        for (int kk = 0; kk < 16; kk++) {
            float4 a0 = *(const float4*)&As[kk][ty * 8];
            float4 a1 = *(const float4*)&As[kk][ty * 8 + 4];
            float4 b0 = *(const float4*)&Bs[kk][tx * 8];
            float4 b1 = *(const float4*)&Bs[kk][tx * 8 + 4];
            float av[8] = {a0.x,a0.y,a0.z,a0.w,a1.x,a1.y,a1.z,a1.w};
            float bv[8] = {b0.x,b0.y,b0.z,b0.w,b1.x,b1.y,b1.z,b1.w};
#pragma unroll
            for (int i = 0; i < 8; i++)
#pragma unroll
                for (int j = 0; j < 8; j++) acc[i][j] += av[i] * bv[j];
        }
    }
#pragma unroll
    for (int i = 0; i < 8; i++) {
        int row = m0 + ty * 8 + i;
        float n1 = g_N[b * 512 + row];
        float* dst = g_SIM + ((size_t)b * 512 + row) * 512 + n0 + tx * 8;
#pragma unroll
        for (int j = 0; j < 8; j++) {
            float n2 = g_N[(32 + b) * 512 + n0 + tx * 8 + j];
            dst[j] = acc[i][j] / fmaxf(n1 * n2, 1e-8f);
        }
    }
}

// ---- K6: max/argmax over axis 2 ----
__global__ void rowmax_kernel() {
    int b = blockIdx.x;
    int w = threadIdx.x >> 5, lane = threadIdx.x & 31;
    int i = blockIdx.y * 8 + w;
    const float* row = g_SIM + ((size_t)b * 512 + i) * 512;
    float best = -1e30f; int bi = 0;
    for (int j = lane; j < 512; j += 32) {
        float v = row[j];
        if (v > best) { best = v; bi = j; }
    }
#pragma unroll
    for (int off = 16; off; off >>= 1) {
        float v = __shfl_down_sync(0xffffffffu, best, off);
        int ii = __shfl_down_sync(0xffffffffu, bi, off);
        if (v > best || (v == best && ii < bi)) { best = v; bi = ii; }
    }
    if (lane == 0) {
        g_MS1[b * 512 + i] = best;
        g_RL1[b * 512 + i] = (float)(i - bi);
    }
}

// ---- K7: max/argmax over axis 1 ----
__global__ void colmax_kernel() {
    int b = blockIdx.x, j0 = blockIdx.y * 32;
    int g = threadIdx.x >> 5, j = threadIdx.x & 31;
    float best = -1e30f; int bi = 0;
    const float* S = g_SIM + (size_t)b * 512 * 512;
    for (int i = g; i < 512; i += 8) {
        float v = S[(size_t)i * 512 + j0 + j];
        if (v > best) { best = v; bi = i; }
    }
    __shared__ float sm[256];
    __shared__ int   si[256];
    sm[threadIdx.x] = best; si[threadIdx.x] = bi;
    __syncthreads();
    if (g == 0) {
        for (int gg = 1; gg < 8; gg++) {
            float v = sm[gg * 32 + j]; int ii = si[gg * 32 + j];
            if (v > best || (v == best && ii < bi)) { best = v; bi = ii; }
        }
        int jj = j0 + j;
        g_MS2[b * 512 + jj] = best;
        g_RL2[b * 512 + jj] = (float)(jj - bi);
    }
}

// ---- K8: conv branches + BN + ReLU + maxpool ----
__global__ void branch_kernel(const float* __restrict__ cw0, const float* __restrict__ cw1,
                              const float* __restrict__ cw2, const float* __restrict__ cb,
                              const float* __restrict__ bng, const float* __restrict__ bnb,
                              const float* __restrict__ bnm, const float* __restrict__ bnv) {
    int b = blockIdx.x, br = blockIdx.y;
    __shared__ float xs[2][512];
    const float* ms = br ? g_MS2 : g_MS1;
    const float* rl = br ? g_RL2 : g_RL1;
    for (int i = threadIdx.x; i < 512; i += 384) {
        xs[0][i] = ms[b * 512 + i];
        xs[1][i] = rl[b * 512 + i];
    }
    __syncthreads();
    int t = threadIdx.x;
    int ci = t >> 7, o = t & 127;
    int ks = 2 + ci;
    const float* w = (ci == 0) ? cw0 : ((ci == 1) ? cw1 : cw2);
    float wreg[2][4];
    for (int c = 0; c < 2; c++)
        for (int q = 0; q < 4; q++) wreg[c][q] = (q < ks) ? w[(o * 2 + c) * ks + q] : 0.f;
    float bias = cb[ci * 128 + o];
    float inv = rsqrtf(bnv[ci * 128 + o] + 1e-5f);
    float sc = bng[ci * 128 + o] * inv;
    float sh = bnb[ci * 128 + o] + (bias - bnm[ci * 128 + o]) * sc;
    float best = -1e30f;
    int P = 512 - ks + 1;
    for (int p = 0; p < P; p++) {
        float v = 0.f;
        for (int q = 0; q < ks; q++) {
            v += wreg[0][q] * xs[0][p + q];
            v += wreg[1][q] * xs[1][p + q];
        }
        v = fmaxf(v * sc + sh, 0.f);
        best = fmaxf(best, v);
    }
    g_FEAT[b * 768 + br * 384 + ci * 128 + o] = best;
}

// ---- K9: fc + softmax ----
__global__ void fc_kernel(const float* __restrict__ fw, const float* __restrict__ fb,
                          float* __restrict__ out) {
    int b = blockIdx.x;
    int w = threadIdx.x >> 5, lane = threadIdx.x & 31;
    __shared__ float lg[2];
    if (w < 2) {
        float s = 0.f;
        for (int k = lane; k < 768; k += 32) s += fw[w * 768 + k] * g_FEAT[b * 768 + k];
#pragma unroll
        for (int off = 16; off; off >>= 1) s += __shfl_down_sync(0xffffffffu, s, off);
        if (lane == 0) lg[w] = s + fb[w];
    }
    __syncthreads();
    if (threadIdx.x == 0) {
        float m = fmaxf(lg[0], lg[1]);
        float e0 = expf(lg[0] - m), e1 = expf(lg[1] - m);
        float inv = 1.f / (e0 + e1);
        out[b * 2 + 0] = e0 * inv;
        out[b * 2 + 1] = e1 * inv;
    }
}

extern "C" void kernel_launch(void* const* d_in, const int* in_sizes, int n_in,
                              void* d_out, int out_size) {
    const int* word1 = (const int*)d_in[0];
    const int* word2 = (const int*)d_in[1];
    const int* piny1 = (const int*)d_in[2];
    const int* piny2 = (const int*)d_in[3];
    const int* len1  = (const int*)d_in[4];
    const int* len2  = (const int*)d_in[5];
    const int* tb1   = (const int*)d_in[6];
    const int* te1   = (const int*)d_in[7];
    const int* tb2   = (const int*)d_in[8];
    const int* te2   = (const int*)d_in[9];
    const float* ew   = (const float*)d_in[10];
    const float* ep   = (const float*)d_in[11];
    const float* pe   = (const float*)d_in[12];
    const float* wih  = (const float*)d_in[13];
    const float* whh  = (const float*)d_in[14];
    const float* bih  = (const float*)d_in[15];
    const float* bhh  = (const float*)d_in[16];
    const float* cw0  = (const float*)d_in[17];
    const float* cw1  = (const float*)d_in[18];
    const float* cw2  = (const float*)d_in[19];
    const float* cb   = (const float*)d_in[20];
    const float* bng  = (const float*)d_in[21];
    const float* bnb  = (const float*)d_in[22];
    const float* bnm  = (const float*)d_in[23];
    const float* bnv  = (const float*)d_in[24];
    const float* fw   = (const float*)d_in[25];
    const float* fb   = (const float*)d_in[26];
    float* out = (float*)d_out;

    pe_tables<<<dim3(24, 32, 5), 256>>>(pe, wih);
    embed_pack<<<dim3(64, 512), 128>>>(word1, word2, piny1, piny2, ew, ep);
    gemm_gi<<<dim3(24, 256), 256>>>(wih, bih, tb1, te1, tb2, te2);
    gru_persist<<<GRU_BLOCKS, 64>>>(whh, bhh, len1, len2);
    norms_kernel<<<dim3(64, 64), 256>>>();
    sim_gemm<<<dim3(4, 4, 32), 256>>>();
    rowmax_kernel<<<dim3(32, 64), 256>>>();
    colmax_kernel<<<dim3(32, 16), 256>>>();
    branch_kernel<<<dim3(32, 2), 384>>>(cw0, cw1, cw2, cb, bng, bnb, bnm, bnv);
    fc_kernel<<<32, 64>>>(fw, fb, out);
}